// round 13
// baseline (speedup 1.0000x reference)
#include <cuda_runtime.h>
#include <cuda_fp16.h>
#include <cuda_bf16.h>

// CBOW hierarchical-softmax loss.
// Inputs (metadata order):
//   d_in[0] context_idxs  int32 [B, C]   B=65536, C=10
//   d_in[1] path_nodes    int32 [B, D]   D=18
//   d_in[2] codes         int32 [B, D]
//   d_in[3] in_embed      f32   [V, E]   V=100000, E=128
//   d_in[4] node_embed    f32   [N, E]   N=99999
// Output: loss f32 [B]
//
// R13 = R12 (fp16 tables in __device__ scratch; main kernel 49.5us, convert
//       24.7us) with two targeted fixes:
//       (a) convert kernel: 2x float4 -> 1x uint4 16B stores (half the store
//           instructions, pure streaming),
//       (b) main kernel: split each 256B row gather into 2x LDG.32 (1 cache
//           line each) -- within-LDG wavefront replays (2.07cyc) become
//           cross-LDG wavefronts (1.0cyc); L1 was the top pipe at 77.9%.

#define B_ 65536
#define C_ 10
#define D_ 18
#define E_ 128
#define V_ 100000
#define N_ 99999
#define EPS_ 1e-9f

typedef unsigned long long u64;

// fp16 tables (scratch). Row = E_/8 = 16 uint4 = 64 uint (half2) = 128 halves.
__device__ uint4 g_in16[V_ * E_ / 8];   // 25.6 MB
__device__ uint4 g_nd16[N_ * E_ / 8];   // 25.6 MB

__device__ __forceinline__ u64 f32x2_add(u64 a, u64 b) {
    u64 r; asm("add.rn.f32x2 %0, %1, %2;" : "=l"(r) : "l"(a), "l"(b)); return r;
}
__device__ __forceinline__ u64 pack2(float lo, float hi) {
    u64 r; asm("mov.b64 %0, {%1, %2};" : "=l"(r) : "f"(lo), "f"(hi)); return r;
}
__device__ __forceinline__ float2 unpack2(u64 v) {
    float2 f; asm("mov.b64 {%0, %1}, %2;" : "=f"(f.x), "=f"(f.y) : "l"(v)); return f;
}
__device__ __forceinline__ u64 shfl_xor_u64(u64 v, int o) {
    uint2 t; asm("mov.b64 {%0, %1}, %2;" : "=r"(t.x), "=r"(t.y) : "l"(v));
    t.x = __shfl_xor_sync(0xFFFFFFFFu, t.x, o);
    t.y = __shfl_xor_sync(0xFFFFFFFFu, t.y, o);
    u64 r; asm("mov.b64 %0, {%1, %2};" : "=l"(r) : "r"(t.x), "r"(t.y));
    return r;
}
__device__ __forceinline__ float2 h2f2(unsigned h) {
    __half2 hh = *reinterpret_cast<__half2*>(&h);
    return __half22float2(hh);
}

// ---------------- prologue: f32 tables -> fp16 scratch ----------------
// Each thread: 2x float4 (32B read) -> 1x uint4 (16B = 8 halves) store.
__global__ void __launch_bounds__(256) convert_kernel(
    const float4* __restrict__ inA,   // in_embed, V_*E_/4 float4
    const float4* __restrict__ inB)   // node_embed, N_*E_/4 float4
{
    const int nA8 = V_ * E_ / 8;              // uint4 count for in_embed
    const int nTot = nA8 + N_ * E_ / 8;
    int i = blockIdx.x * blockDim.x + threadIdx.x;
    if (i >= nTot) return;

    const float4* src;
    uint4* dst;
    if (i < nA8) {
        src = inA + 2 * (size_t)i;
        dst = &g_in16[i];
    } else {
        src = inB + 2 * (size_t)(i - nA8);
        dst = &g_nd16[i - nA8];
    }
    float4 f0 = __ldg(src);
    float4 f1 = __ldg(src + 1);
    __half2 h0 = __floats2half2_rn(f0.x, f0.y);
    __half2 h1 = __floats2half2_rn(f0.z, f0.w);
    __half2 h2 = __floats2half2_rn(f1.x, f1.y);
    __half2 h3 = __floats2half2_rn(f1.z, f1.w);
    uint4 o;
    o.x = *reinterpret_cast<unsigned*>(&h0);
    o.y = *reinterpret_cast<unsigned*>(&h1);
    o.z = *reinterpret_cast<unsigned*>(&h2);
    o.w = *reinterpret_cast<unsigned*>(&h3);
    // streaming store (no L2 pollution beyond what's needed)
    asm volatile("st.global.cs.v4.u32 [%0], {%1, %2, %3, %4};"
                 :: "l"(dst), "r"(o.x), "r"(o.y), "r"(o.z), "r"(o.w));
}

// ---------------- main: fp16 rows, 2x single-line LDG.32 per row ----------------
__global__ void __launch_bounds__(256) cbow_hs_kernel(
    const int* __restrict__ ctx,
    const int* __restrict__ path,
    const int* __restrict__ codes,
    float* __restrict__ out)
{
    const int warp = (blockIdx.x * blockDim.x + threadIdx.x) >> 5;
    const int lane = threadIdx.x & 31;
    if (warp >= B_) return;

    // fp16 row = 64 uint (half2); lane owns uint[lane] (halves 2l,2l+1) and
    // uint[32+lane] (halves 64+2l, 64+2l+1). Each LDG.32 touches ONE line.
    const unsigned* __restrict__ in16 = reinterpret_cast<const unsigned*>(g_in16);
    const unsigned* __restrict__ nd16 = reinterpret_cast<const unsigned*>(g_nd16);

    // ---- per-lane code: one coalesced 72B LDG per warp ----
    int code_l = 0;
    if (lane < D_) code_l = __ldg(&codes[warp * D_ + lane]);

    // ---- context indices: 5 x int2 ----
    const int2* __restrict__ ctx2 = reinterpret_cast<const int2*>(ctx + warp * C_);
    int cidx[C_];
#pragma unroll
    for (int j = 0; j < C_ / 2; j++) {
        int2 c = __ldg(&ctx2[j]);
        cidx[2 * j]     = c.x;
        cidx[2 * j + 1] = c.y;
    }

    // ---- context mean: 10 rows x 2 single-line loads ----
    float v0 = 0.f, v1 = 0.f, v2 = 0.f, v3 = 0.f;
#pragma unroll
    for (int j = 0; j < C_; j++) {
        const unsigned* r = in16 + (size_t)cidx[j] * (E_ / 2) + lane;
        unsigned lo = __ldg(r);
        unsigned hi = __ldg(r + 32);
        float2 a = h2f2(lo);
        float2 b = h2f2(hi);
        v0 += a.x; v1 += a.y; v2 += b.x; v3 += b.y;
    }
    const float inv = 1.0f / (float)C_;
    v0 *= inv; v1 *= inv; v2 *= inv; v3 *= inv;

    // ---- path indices: 9 x int2 ----
    const int2* __restrict__ pn2 = reinterpret_cast<const int2*>(path + warp * D_);
    int pn[D_];
#pragma unroll
    for (int j = 0; j < D_ / 2; j++) {
        int2 p = __ldg(&pn2[j]);
        pn[2 * j] = p.x; pn[2 * j + 1] = p.y;
    }

    // ---- 18 node rows x 2 single-line loads -> 9 packed partials ----
    u64 pair[D_ / 2];
#pragma unroll
    for (int j = 0; j < D_ / 2; j++) {
        const unsigned* r0 = nd16 + (size_t)pn[2 * j]     * (E_ / 2) + lane;
        const unsigned* r1 = nd16 + (size_t)pn[2 * j + 1] * (E_ / 2) + lane;
        unsigned l0 = __ldg(r0), h0 = __ldg(r0 + 32);
        unsigned l1 = __ldg(r1), h1 = __ldg(r1 + 32);
        float2 a0 = h2f2(l0), b0 = h2f2(h0);
        float2 a1 = h2f2(l1), b1 = h2f2(h1);
        float p0 = fmaf(a0.x, v0, fmaf(a0.y, v1, fmaf(b0.x, v2, b0.y * v3)));
        float p1 = fmaf(a1.x, v0, fmaf(a1.y, v1, fmaf(b1.x, v2, b1.y * v3)));
        pair[j] = pack2(p0, p1);
    }

    // ---- pair-packed butterfly: 9 u64 reduced across lanes in 5 steps ----
#pragma unroll
    for (int o = 16; o > 0; o >>= 1) {
#pragma unroll
        for (int j = 0; j < D_ / 2; j++)
            pair[j] = f32x2_add(pair[j], shfl_xor_u64(pair[j], o));
    }

    // ---- lane d takes logit s_d ----
    const int mypair_idx = lane >> 1;
    u64 mypair = pair[0];
#pragma unroll
    for (int j = 1; j < D_ / 2; j++)
        mypair = (j == mypair_idx) ? pair[j] : mypair;
    float2 sp = unpack2(mypair);
    float s = (lane & 1) ? sp.y : sp.x;

    // ---- epilogue once per warp (3 MUFU total) ----
    float x = code_l ? s : -s;   // p = sigmoid(x) if code==1 else sigmoid(-x)
    float sig = __fdividef(1.0f, 1.0f + __expf(-x));
    float term = __logf(sig + EPS_);
    term = (lane < D_) ? term : 0.f;

#pragma unroll
    for (int o = 16; o > 0; o >>= 1)
        term += __shfl_xor_sync(0xFFFFFFFFu, term, o);

    if (lane == 0)
        out[warp] = -term;
}

extern "C" void kernel_launch(void* const* d_in, const int* in_sizes, int n_in,
                              void* d_out, int out_size)
{
    const int*   ctx      = (const int*)d_in[0];
    const int*   path     = (const int*)d_in[1];
    const int*   codes    = (const int*)d_in[2];
    const float* in_emb   = (const float*)d_in[3];
    const float* node_emb = (const float*)d_in[4];
    float*       out      = (float*)d_out;

    // 1) convert both tables to fp16 scratch (16B stores)
    {
        const int nTot = (V_ + N_) * E_ / 8;   // uint4 count
        const int threads = 256;
        const int blocks = (nTot + threads - 1) / threads;
        convert_kernel<<<blocks, threads>>>(
            reinterpret_cast<const float4*>(in_emb),
            reinterpret_cast<const float4*>(node_emb));
    }

    // 2) main gather pass on fp16 rows
    {
        const int threads = 256;               // 8 warps/block
        const int total   = B_ * 32;
        const int blocks  = (total + threads - 1) / threads;
        cbow_hs_kernel<<<blocks, threads>>>(ctx, path, codes, out);
    }
}

// round 14
// speedup vs baseline: 1.1314x; 1.1314x over previous
#include <cuda_runtime.h>
#include <cuda_fp16.h>
#include <cuda_bf16.h>

// CBOW hierarchical-softmax loss.
// Inputs (metadata order):
//   d_in[0] context_idxs  int32 [B, C]   B=65536, C=10
//   d_in[1] path_nodes    int32 [B, D]   D=18
//   d_in[2] codes         int32 [B, D]
//   d_in[3] in_embed      f32   [V, E]   V=100000, E=128
//   d_in[4] node_embed    f32   [N, E]   N=99999
// Output: loss f32 [B]
//
// R14: fp16 tables (R12/R13 convert kernel, 22us) + LDG.128 PAIRED gathers:
//      a fp16 row is 256B = 16 lanes x 16B, so ONE LDG.128 per warp fetches
//      TWO rows (half-warp 0 -> even row of pair, half-warp 1 -> odd).
//      28 row-loads/warp -> 14, same 56 lines. At fp16 this costs only
//      16B/lane of registers (R6's f32 version needed 32B/lane -> regs=124);
//      launch_bounds(256,4) caps at 64 regs = full 32-warp occupancy.
//      Half-warp 4-step dot reduction + R6 routing; epilogue unchanged.

#define B_ 65536
#define C_ 10
#define D_ 18
#define E_ 128
#define V_ 100000
#define N_ 99999
#define EPS_ 1e-9f

// fp16 tables (scratch). Row = E_/8 = 16 uint4 = 128 halves = 256B.
__device__ uint4 g_in16[V_ * E_ / 8];   // 25.6 MB
__device__ uint4 g_nd16[N_ * E_ / 8];   // 25.6 MB

__device__ __forceinline__ float2 h2f2(unsigned h) {
    __half2 hh = *reinterpret_cast<__half2*>(&h);
    return __half22float2(hh);
}

// ---------------- prologue: f32 tables -> fp16 scratch (R13 version) ----------------
__global__ void __launch_bounds__(256) convert_kernel(
    const float4* __restrict__ inA,   // in_embed, V_*E_/4 float4
    const float4* __restrict__ inB)   // node_embed, N_*E_/4 float4
{
    const int nA8 = V_ * E_ / 8;              // uint4 count for in_embed
    const int nTot = nA8 + N_ * E_ / 8;
    int i = blockIdx.x * blockDim.x + threadIdx.x;
    if (i >= nTot) return;

    const float4* src;
    uint4* dst;
    if (i < nA8) {
        src = inA + 2 * (size_t)i;
        dst = &g_in16[i];
    } else {
        src = inB + 2 * (size_t)(i - nA8);
        dst = &g_nd16[i - nA8];
    }
    float4 f0 = __ldg(src);
    float4 f1 = __ldg(src + 1);
    __half2 h0 = __floats2half2_rn(f0.x, f0.y);
    __half2 h1 = __floats2half2_rn(f0.z, f0.w);
    __half2 h2 = __floats2half2_rn(f1.x, f1.y);
    __half2 h3 = __floats2half2_rn(f1.z, f1.w);
    uint4 o;
    o.x = *reinterpret_cast<unsigned*>(&h0);
    o.y = *reinterpret_cast<unsigned*>(&h1);
    o.z = *reinterpret_cast<unsigned*>(&h2);
    o.w = *reinterpret_cast<unsigned*>(&h3);
    asm volatile("st.global.cs.v4.u32 [%0], {%1, %2, %3, %4};"
                 :: "l"(dst), "r"(o.x), "r"(o.y), "r"(o.z), "r"(o.w));
}

// ---------------- main: paired LDG.128 fp16 gathers ----------------
__global__ void __launch_bounds__(256, 4) cbow_hs_kernel(
    const int* __restrict__ ctx,
    const int* __restrict__ path,
    const int* __restrict__ codes,
    float* __restrict__ out)
{
    const int warp = (blockIdx.x * blockDim.x + threadIdx.x) >> 5;
    const int lane = threadIdx.x & 31;
    if (warp >= B_) return;

    const int half   = lane >> 4;        // 0: even row of pair, 1: odd row
    const int lane16 = lane & 15;        // 16B slice within the 256B row

    const uint4* __restrict__ in16 = g_in16;   // row = 16 uint4
    const uint4* __restrict__ nd16 = g_nd16;

    // ---- per-lane code: one coalesced 72B LDG per warp ----
    int code_l = 0;
    if (lane < D_) code_l = __ldg(&codes[warp * D_ + lane]);

    // ---- indices: per-lane row selection by half ----
    const int2* __restrict__ ctx2 = reinterpret_cast<const int2*>(ctx + warp * C_);
    const int2* __restrict__ pn2  = reinterpret_cast<const int2*>(path + warp * D_);
    int csel[C_ / 2];
#pragma unroll
    for (int j = 0; j < C_ / 2; j++) {
        int2 c = __ldg(&ctx2[j]);
        csel[j] = half ? c.y : c.x;
    }
    int psel[D_ / 2];
#pragma unroll
    for (int j = 0; j < D_ / 2; j++) {
        int2 p = __ldg(&pn2[j]);
        psel[j] = half ? p.y : p.x;
    }

    // ---- ctx: 5 paired LDG.128 fetch all 10 rows ----
    uint4 ce[C_ / 2];
#pragma unroll
    for (int j = 0; j < C_ / 2; j++)
        ce[j] = __ldg(&in16[(size_t)csel[j] * (E_ / 8) + lane16]);

    // ---- node rows: 9 paired LDG.128 fetch all 18 rows ----
    uint4 nu[D_ / 2];
#pragma unroll
    for (int j = 0; j < D_ / 2; j++)
        nu[j] = __ldg(&nd16[(size_t)psel[j] * (E_ / 8) + lane16]);

    // ---- mean: in-lane sum of this half's 5 rows, then cross-half add ----
    float v[8] = {0.f, 0.f, 0.f, 0.f, 0.f, 0.f, 0.f, 0.f};
#pragma unroll
    for (int j = 0; j < C_ / 2; j++) {
        float2 a = h2f2(ce[j].x), b = h2f2(ce[j].y);
        float2 c = h2f2(ce[j].z), d = h2f2(ce[j].w);
        v[0] += a.x; v[1] += a.y; v[2] += b.x; v[3] += b.y;
        v[4] += c.x; v[5] += c.y; v[6] += d.x; v[7] += d.y;
    }
    const float inv = 1.0f / (float)C_;
#pragma unroll
    for (int k = 0; k < 8; k++) {
        v[k] += __shfl_xor_sync(0xFFFFFFFFu, v[k], 16);
        v[k] *= inv;
    }

    // ---- per-lane partial dots (8 cols each) ----
    float part[D_ / 2];
#pragma unroll
    for (int j = 0; j < D_ / 2; j++) {
        float2 a = h2f2(nu[j].x), b = h2f2(nu[j].y);
        float2 c = h2f2(nu[j].z), d = h2f2(nu[j].w);
        float s0 = fmaf(a.x, v[0], fmaf(a.y, v[1], fmaf(b.x, v[2], b.y * v[3])));
        float s1 = fmaf(c.x, v[4], fmaf(c.y, v[5], fmaf(d.x, v[6], d.y * v[7])));
        part[j] = s0 + s1;
    }

    // ---- 4-step butterfly within half-warp: s_{2j+half} in all 16 lanes ----
#pragma unroll
    for (int o = 8; o > 0; o >>= 1) {
#pragma unroll
        for (int j = 0; j < D_ / 2; j++)
            part[j] += __shfl_xor_sync(0xFFFFFFFFu, part[j], o);
    }

    // ---- route s_d to lane d (R6 scheme, verified) ----
    // lane l prepares part[l & 15]; lane d reads lane 16*(d&1) + (d>>1).
    const int sel = lane & 15;
    float prep = part[0];
#pragma unroll
    for (int j = 1; j < D_ / 2; j++)
        prep = (sel == j) ? part[j] : prep;
    float s = __shfl_sync(0xFFFFFFFFu, prep, ((lane & 1) << 4) | (lane >> 1));

    // ---- epilogue once per warp (3 MUFU total) ----
    float x = code_l ? s : -s;   // p = sigmoid(x) if code==1 else sigmoid(-x)
    float sig = __fdividef(1.0f, 1.0f + __expf(-x));
    float term = __logf(sig + EPS_);
    term = (lane < D_) ? term : 0.f;

#pragma unroll
    for (int o = 16; o > 0; o >>= 1)
        term += __shfl_xor_sync(0xFFFFFFFFu, term, o);

    if (lane == 0)
        out[warp] = -term;
}

extern "C" void kernel_launch(void* const* d_in, const int* in_sizes, int n_in,
                              void* d_out, int out_size)
{
    const int*   ctx      = (const int*)d_in[0];
    const int*   path     = (const int*)d_in[1];
    const int*   codes    = (const int*)d_in[2];
    const float* in_emb   = (const float*)d_in[3];
    const float* node_emb = (const float*)d_in[4];
    float*       out      = (float*)d_out;

    // 1) convert both tables to fp16 scratch (16B stores)
    {
        const int nTot = (V_ + N_) * E_ / 8;   // uint4 count
        const int threads = 256;
        const int blocks = (nTot + threads - 1) / threads;
        convert_kernel<<<blocks, threads>>>(
            reinterpret_cast<const float4*>(in_emb),
            reinterpret_cast<const float4*>(node_emb));
    }

    // 2) main gather pass on fp16 rows (paired LDG.128)
    {
        const int threads = 256;               // 8 warps/block
        const int total   = B_ * 32;
        const int blocks  = (total + threads - 1) / threads;
        cbow_hs_kernel<<<blocks, threads>>>(ctx, path, codes, out);
    }
}

// round 15
// speedup vs baseline: 1.1631x; 1.0280x over previous
#include <cuda_runtime.h>
#include <cuda_fp16.h>
#include <cuda_bf16.h>

// CBOW hierarchical-softmax loss.
// Inputs (metadata order):
//   d_in[0] context_idxs  int32 [B, C]   B=65536, C=10
//   d_in[1] path_nodes    int32 [B, D]   D=18
//   d_in[2] codes         int32 [B, D]
//   d_in[3] in_embed      f32   [V, E]   V=100000, E=128
//   d_in[4] node_embed    f32   [N, E]   N=99999
// Output: loss f32 [B]
//
// R15 = R14 (fp16 tables + paired LDG.128: one load fetches two 256B rows;
//       main 44.7us, issue-bound on fp32 math at 65% issue / 40% fma) with
//       the FP stream halved via half2 arithmetic:
//       - mean accumulated in HADD2 (cross-half reduce + scale kept fp32)
//       - dot partials via 4-op HFMA2 chains (butterflies/epilogue fp32)
//       ~94 instr/warp saved on the fma pipe. rel_err expected ~7.5-8.5e-4
//       (gate 1e-3; fallback = revert math to fp32, keep structure).

#define B_ 65536
#define C_ 10
#define D_ 18
#define E_ 128
#define V_ 100000
#define N_ 99999
#define EPS_ 1e-9f

// fp16 tables (scratch). Row = E_/8 = 16 uint4 = 128 halves = 256B.
__device__ uint4 g_in16[V_ * E_ / 8];   // 25.6 MB
__device__ uint4 g_nd16[N_ * E_ / 8];   // 25.6 MB

__device__ __forceinline__ __half2 as_h2(unsigned u) {
    return *reinterpret_cast<__half2*>(&u);
}

// ---------------- prologue: f32 tables -> fp16 scratch (R13 version) ----------------
__global__ void __launch_bounds__(256) convert_kernel(
    const float4* __restrict__ inA,   // in_embed, V_*E_/4 float4
    const float4* __restrict__ inB)   // node_embed, N_*E_/4 float4
{
    const int nA8 = V_ * E_ / 8;              // uint4 count for in_embed
    const int nTot = nA8 + N_ * E_ / 8;
    int i = blockIdx.x * blockDim.x + threadIdx.x;
    if (i >= nTot) return;

    const float4* src;
    uint4* dst;
    if (i < nA8) {
        src = inA + 2 * (size_t)i;
        dst = &g_in16[i];
    } else {
        src = inB + 2 * (size_t)(i - nA8);
        dst = &g_nd16[i - nA8];
    }
    float4 f0 = __ldg(src);
    float4 f1 = __ldg(src + 1);
    __half2 h0 = __floats2half2_rn(f0.x, f0.y);
    __half2 h1 = __floats2half2_rn(f0.z, f0.w);
    __half2 h2 = __floats2half2_rn(f1.x, f1.y);
    __half2 h3 = __floats2half2_rn(f1.z, f1.w);
    uint4 o;
    o.x = *reinterpret_cast<unsigned*>(&h0);
    o.y = *reinterpret_cast<unsigned*>(&h1);
    o.z = *reinterpret_cast<unsigned*>(&h2);
    o.w = *reinterpret_cast<unsigned*>(&h3);
    asm volatile("st.global.cs.v4.u32 [%0], {%1, %2, %3, %4};"
                 :: "l"(dst), "r"(o.x), "r"(o.y), "r"(o.z), "r"(o.w));
}

// ---------------- main: paired LDG.128 fp16 gathers, half2 math ----------------
__global__ void __launch_bounds__(256, 4) cbow_hs_kernel(
    const int* __restrict__ ctx,
    const int* __restrict__ path,
    const int* __restrict__ codes,
    float* __restrict__ out)
{
    const int warp = (blockIdx.x * blockDim.x + threadIdx.x) >> 5;
    const int lane = threadIdx.x & 31;
    if (warp >= B_) return;

    const int half   = lane >> 4;        // 0: even row of pair, 1: odd row
    const int lane16 = lane & 15;        // 16B slice within the 256B row

    const uint4* __restrict__ in16 = g_in16;   // row = 16 uint4
    const uint4* __restrict__ nd16 = g_nd16;

    // ---- per-lane code: one coalesced 72B LDG per warp ----
    int code_l = 0;
    if (lane < D_) code_l = __ldg(&codes[warp * D_ + lane]);

    // ---- indices: per-lane row selection by half ----
    const int2* __restrict__ ctx2 = reinterpret_cast<const int2*>(ctx + warp * C_);
    const int2* __restrict__ pn2  = reinterpret_cast<const int2*>(path + warp * D_);
    int csel[C_ / 2];
#pragma unroll
    for (int j = 0; j < C_ / 2; j++) {
        int2 c = __ldg(&ctx2[j]);
        csel[j] = half ? c.y : c.x;
    }
    int psel[D_ / 2];
#pragma unroll
    for (int j = 0; j < D_ / 2; j++) {
        int2 p = __ldg(&pn2[j]);
        psel[j] = half ? p.y : p.x;
    }

    // ---- ctx: 5 paired LDG.128 fetch all 10 rows ----
    uint4 ce[C_ / 2];
#pragma unroll
    for (int j = 0; j < C_ / 2; j++)
        ce[j] = __ldg(&in16[(size_t)csel[j] * (E_ / 8) + lane16]);

    // ---- node rows: 9 paired LDG.128 fetch all 18 rows ----
    uint4 nu[D_ / 2];
#pragma unroll
    for (int j = 0; j < D_ / 2; j++)
        nu[j] = __ldg(&nd16[(size_t)psel[j] * (E_ / 8) + lane16]);

    // ---- mean: accumulate this half's 5 rows in half2 (4 HADD2/row) ----
    __half2 hv0 = as_h2(ce[0].x), hv1 = as_h2(ce[0].y);
    __half2 hv2 = as_h2(ce[0].z), hv3 = as_h2(ce[0].w);
#pragma unroll
    for (int j = 1; j < C_ / 2; j++) {
        hv0 = __hadd2(hv0, as_h2(ce[j].x));
        hv1 = __hadd2(hv1, as_h2(ce[j].y));
        hv2 = __hadd2(hv2, as_h2(ce[j].z));
        hv3 = __hadd2(hv3, as_h2(ce[j].w));
    }
    // cross-half reduce + scale in fp32 (precision-critical)
    float v[8];
    {
        float2 a = __half22float2(hv0), b = __half22float2(hv1);
        float2 c = __half22float2(hv2), d = __half22float2(hv3);
        v[0] = a.x; v[1] = a.y; v[2] = b.x; v[3] = b.y;
        v[4] = c.x; v[5] = c.y; v[6] = d.x; v[7] = d.y;
    }
    const float inv = 1.0f / (float)C_;
#pragma unroll
    for (int k = 0; k < 8; k++) {
        v[k] += __shfl_xor_sync(0xFFFFFFFFu, v[k], 16);
        v[k] *= inv;
    }
    // requantize v to half2 once for the HFMA2 dot chains
    __half2 vh0 = __floats2half2_rn(v[0], v[1]);
    __half2 vh1 = __floats2half2_rn(v[2], v[3]);
    __half2 vh2 = __floats2half2_rn(v[4], v[5]);
    __half2 vh3 = __floats2half2_rn(v[6], v[7]);

    // ---- per-lane partial dots: 4-op HFMA2 chain per row ----
    float part[D_ / 2];
#pragma unroll
    for (int j = 0; j < D_ / 2; j++) {
        __half2 acc = __hmul2(as_h2(nu[j].x), vh0);
        acc = __hfma2(as_h2(nu[j].y), vh1, acc);
        acc = __hfma2(as_h2(nu[j].z), vh2, acc);
        acc = __hfma2(as_h2(nu[j].w), vh3, acc);
        float2 f = __half22float2(acc);
        part[j] = f.x + f.y;
    }

    // ---- 4-step butterfly within half-warp (fp32) ----
#pragma unroll
    for (int o = 8; o > 0; o >>= 1) {
#pragma unroll
        for (int j = 0; j < D_ / 2; j++)
            part[j] += __shfl_xor_sync(0xFFFFFFFFu, part[j], o);
    }

    // ---- route s_d to lane d (R6/R14 scheme) ----
    const int sel = lane & 15;
    float prep = part[0];
#pragma unroll
    for (int j = 1; j < D_ / 2; j++)
        prep = (sel == j) ? part[j] : prep;
    float s = __shfl_sync(0xFFFFFFFFu, prep, ((lane & 1) << 4) | (lane >> 1));

    // ---- epilogue once per warp (3 MUFU total) ----
    float x = code_l ? s : -s;   // p = sigmoid(x) if code==1 else sigmoid(-x)
    float sig = __fdividef(1.0f, 1.0f + __expf(-x));
    float term = __logf(sig + EPS_);
    term = (lane < D_) ? term : 0.f;

#pragma unroll
    for (int o = 16; o > 0; o >>= 1)
        term += __shfl_xor_sync(0xFFFFFFFFu, term, o);

    if (lane == 0)
        out[warp] = -term;
}

extern "C" void kernel_launch(void* const* d_in, const int* in_sizes, int n_in,
                              void* d_out, int out_size)
{
    const int*   ctx      = (const int*)d_in[0];
    const int*   path     = (const int*)d_in[1];
    const int*   codes    = (const int*)d_in[2];
    const float* in_emb   = (const float*)d_in[3];
    const float* node_emb = (const float*)d_in[4];
    float*       out      = (float*)d_out;

    // 1) convert both tables to fp16 scratch (16B stores)
    {
        const int nTot = (V_ + N_) * E_ / 8;   // uint4 count
        const int threads = 256;
        const int blocks = (nTot + threads - 1) / threads;
        convert_kernel<<<blocks, threads>>>(
            reinterpret_cast<const float4*>(in_emb),
            reinterpret_cast<const float4*>(node_emb));
    }

    // 2) main gather pass on fp16 rows (paired LDG.128, half2 math)
    {
        const int threads = 256;               // 8 warps/block
        const int total   = B_ * 32;
        const int blocks  = (total + threads - 1) / threads;
        cbow_hs_kernel<<<blocks, threads>>>(ctx, path, codes, out);
    }
}

// round 16
// speedup vs baseline: 1.2016x; 1.0331x over previous
#include <cuda_runtime.h>
#include <cuda_fp16.h>
#include <cuda_bf16.h>

// CBOW hierarchical-softmax loss.
// Inputs (metadata order):
//   d_in[0] context_idxs  int32 [B, C]   B=65536, C=10
//   d_in[1] path_nodes    int32 [B, D]   D=18
//   d_in[2] codes         int32 [B, D]
//   d_in[3] in_embed      f32   [V, E]   V=100000, E=128
//   d_in[4] node_embed    f32   [N, E]   N=99999
// Output: loss f32 [B]
//
// R16 = R15 (fp16 tables, paired LDG.128, half2 math) with the register
//       peak cut to raise occupancy: main was regs=64 -> only 32 warps/SM
//       (occ 44.5%) because 14 uint4 gathers sat resident at once.
//       New schedule: ce[5] -> nu[0..3] -> consume ce into mean (frees 20
//       regs) -> nu[4..8] -> finish. Peak ~9-10 wide loads in flight;
//       launch_bounds(256,5) caps regs at 51 -> 40 warps/SM (occ ~62%).
//       Main's LTS floor is 37us; more warps pushes delivery toward cap.

#define B_ 65536
#define C_ 10
#define D_ 18
#define E_ 128
#define V_ 100000
#define N_ 99999
#define EPS_ 1e-9f

// fp16 tables (scratch). Row = E_/8 = 16 uint4 = 128 halves = 256B.
__device__ uint4 g_in16[V_ * E_ / 8];   // 25.6 MB
__device__ uint4 g_nd16[N_ * E_ / 8];   // 25.6 MB

__device__ __forceinline__ __half2 as_h2(unsigned u) {
    return *reinterpret_cast<__half2*>(&u);
}

// ---------------- prologue: f32 tables -> fp16 scratch ----------------
__global__ void __launch_bounds__(256) convert_kernel(
    const float4* __restrict__ inA,   // in_embed, V_*E_/4 float4
    const float4* __restrict__ inB)   // node_embed, N_*E_/4 float4
{
    const int nA8 = V_ * E_ / 8;              // uint4 count for in_embed
    const int nTot = nA8 + N_ * E_ / 8;
    int i = blockIdx.x * blockDim.x + threadIdx.x;
    if (i >= nTot) return;

    const float4* src;
    uint4* dst;
    if (i < nA8) {
        src = inA + 2 * (size_t)i;
        dst = &g_in16[i];
    } else {
        src = inB + 2 * (size_t)(i - nA8);
        dst = &g_nd16[i - nA8];
    }
    float4 f0 = __ldg(src);
    float4 f1 = __ldg(src + 1);
    __half2 h0 = __floats2half2_rn(f0.x, f0.y);
    __half2 h1 = __floats2half2_rn(f0.z, f0.w);
    __half2 h2 = __floats2half2_rn(f1.x, f1.y);
    __half2 h3 = __floats2half2_rn(f1.z, f1.w);
    uint4 o;
    o.x = *reinterpret_cast<unsigned*>(&h0);
    o.y = *reinterpret_cast<unsigned*>(&h1);
    o.z = *reinterpret_cast<unsigned*>(&h2);
    o.w = *reinterpret_cast<unsigned*>(&h3);
    asm volatile("st.global.cs.v4.u32 [%0], {%1, %2, %3, %4};"
                 :: "l"(dst), "r"(o.x), "r"(o.y), "r"(o.z), "r"(o.w));
}

// ---------------- main: paired LDG.128 fp16 gathers, half2 math ----------------
__global__ void __launch_bounds__(256, 5) cbow_hs_kernel(
    const int* __restrict__ ctx,
    const int* __restrict__ path,
    const int* __restrict__ codes,
    float* __restrict__ out)
{
    const int warp = (blockIdx.x * blockDim.x + threadIdx.x) >> 5;
    const int lane = threadIdx.x & 31;
    if (warp >= B_) return;

    const int half   = lane >> 4;        // 0: even row of pair, 1: odd row
    const int lane16 = lane & 15;        // 16B slice within the 256B row

    const uint4* __restrict__ in16 = g_in16;   // row = 16 uint4
    const uint4* __restrict__ nd16 = g_nd16;

    // ---- per-lane code: one coalesced 72B LDG per warp ----
    int code_l = 0;
    if (lane < D_) code_l = __ldg(&codes[warp * D_ + lane]);

    // ---- indices: per-lane row selection by half ----
    const int2* __restrict__ ctx2 = reinterpret_cast<const int2*>(ctx + warp * C_);
    const int2* __restrict__ pn2  = reinterpret_cast<const int2*>(path + warp * D_);
    int csel[C_ / 2];
#pragma unroll
    for (int j = 0; j < C_ / 2; j++) {
        int2 c = __ldg(&ctx2[j]);
        csel[j] = half ? c.y : c.x;
    }
    int psel[D_ / 2];
#pragma unroll
    for (int j = 0; j < D_ / 2; j++) {
        int2 p = __ldg(&pn2[j]);
        psel[j] = half ? p.y : p.x;
    }

    // ---- wave 1: ctx rows (5 paired LDG.128 = 20 regs) ----
    uint4 ce[C_ / 2];
#pragma unroll
    for (int j = 0; j < C_ / 2; j++)
        ce[j] = __ldg(&in16[(size_t)csel[j] * (E_ / 8) + lane16]);

    // ---- wave 2a: node pairs 0..3 (16 regs) in flight ----
    uint4 nuA[4];
#pragma unroll
    for (int j = 0; j < 4; j++)
        nuA[j] = __ldg(&nd16[(size_t)psel[j] * (E_ / 8) + lane16]);

    // ---- consume ce into half2 mean accumulators (frees 20 regs) ----
    __half2 hv0 = as_h2(ce[0].x), hv1 = as_h2(ce[0].y);
    __half2 hv2 = as_h2(ce[0].z), hv3 = as_h2(ce[0].w);
#pragma unroll
    for (int j = 1; j < C_ / 2; j++) {
        hv0 = __hadd2(hv0, as_h2(ce[j].x));
        hv1 = __hadd2(hv1, as_h2(ce[j].y));
        hv2 = __hadd2(hv2, as_h2(ce[j].z));
        hv3 = __hadd2(hv3, as_h2(ce[j].w));
    }

    // ---- wave 2b: node pairs 4..8 (20 regs, reusing ce's budget) ----
    uint4 nuB[5];
#pragma unroll
    for (int j = 0; j < 5; j++)
        nuB[j] = __ldg(&nd16[(size_t)psel[4 + j] * (E_ / 8) + lane16]);

    // ---- finish mean: cross-half reduce + scale in fp32 ----
    float v[8];
    {
        float2 a = __half22float2(hv0), b = __half22float2(hv1);
        float2 c = __half22float2(hv2), d = __half22float2(hv3);
        v[0] = a.x; v[1] = a.y; v[2] = b.x; v[3] = b.y;
        v[4] = c.x; v[5] = c.y; v[6] = d.x; v[7] = d.y;
    }
    const float inv = 1.0f / (float)C_;
#pragma unroll
    for (int k = 0; k < 8; k++) {
        v[k] += __shfl_xor_sync(0xFFFFFFFFu, v[k], 16);
        v[k] *= inv;
    }
    __half2 vh0 = __floats2half2_rn(v[0], v[1]);
    __half2 vh1 = __floats2half2_rn(v[2], v[3]);
    __half2 vh2 = __floats2half2_rn(v[4], v[5]);
    __half2 vh3 = __floats2half2_rn(v[6], v[7]);

    // ---- dots: batch A then batch B (HFMA2 chains) ----
    float part[D_ / 2];
#pragma unroll
    for (int j = 0; j < 4; j++) {
        __half2 acc = __hmul2(as_h2(nuA[j].x), vh0);
        acc = __hfma2(as_h2(nuA[j].y), vh1, acc);
        acc = __hfma2(as_h2(nuA[j].z), vh2, acc);
        acc = __hfma2(as_h2(nuA[j].w), vh3, acc);
        float2 f = __half22float2(acc);
        part[j] = f.x + f.y;
    }
#pragma unroll
    for (int j = 0; j < 5; j++) {
        __half2 acc = __hmul2(as_h2(nuB[j].x), vh0);
        acc = __hfma2(as_h2(nuB[j].y), vh1, acc);
        acc = __hfma2(as_h2(nuB[j].z), vh2, acc);
        acc = __hfma2(as_h2(nuB[j].w), vh3, acc);
        float2 f = __half22float2(acc);
        part[4 + j] = f.x + f.y;
    }

    // ---- 4-step butterfly within half-warp (fp32) ----
#pragma unroll
    for (int o = 8; o > 0; o >>= 1) {
#pragma unroll
        for (int j = 0; j < D_ / 2; j++)
            part[j] += __shfl_xor_sync(0xFFFFFFFFu, part[j], o);
    }

    // ---- route s_d to lane d (R6/R14 scheme) ----
    const int sel = lane & 15;
    float prep = part[0];
#pragma unroll
    for (int j = 1; j < D_ / 2; j++)
        prep = (sel == j) ? part[j] : prep;
    float s = __shfl_sync(0xFFFFFFFFu, prep, ((lane & 1) << 4) | (lane >> 1));

    // ---- epilogue once per warp (3 MUFU total) ----
    float x = code_l ? s : -s;   // p = sigmoid(x) if code==1 else sigmoid(-x)
    float sig = __fdividef(1.0f, 1.0f + __expf(-x));
    float term = __logf(sig + EPS_);
    term = (lane < D_) ? term : 0.f;

#pragma unroll
    for (int o = 16; o > 0; o >>= 1)
        term += __shfl_xor_sync(0xFFFFFFFFu, term, o);

    if (lane == 0)
        out[warp] = -term;
}

extern "C" void kernel_launch(void* const* d_in, const int* in_sizes, int n_in,
                              void* d_out, int out_size)
{
    const int*   ctx      = (const int*)d_in[0];
    const int*   path     = (const int*)d_in[1];
    const int*   codes    = (const int*)d_in[2];
    const float* in_emb   = (const float*)d_in[3];
    const float* node_emb = (const float*)d_in[4];
    float*       out      = (float*)d_out;

    // 1) convert both tables to fp16 scratch (16B stores)
    {
        const int nTot = (V_ + N_) * E_ / 8;   // uint4 count
        const int threads = 256;
        const int blocks = (nTot + threads - 1) / threads;
        convert_kernel<<<blocks, threads>>>(
            reinterpret_cast<const float4*>(in_emb),
            reinterpret_cast<const float4*>(node_emb));
    }

    // 2) main gather pass on fp16 rows (paired LDG.128, half2 math)
    {
        const int threads = 256;               // 8 warps/block
        const int total   = B_ * 32;
        const int blocks  = (total + threads - 1) / threads;
        cbow_hs_kernel<<<blocks, threads>>>(ctx, path, codes, out);
    }
}

// round 17
// speedup vs baseline: 1.3331x; 1.1095x over previous
#include <cuda_runtime.h>
#include <cuda_fp16.h>
#include <cuda_bf16.h>

// CBOW hierarchical-softmax loss.
// Inputs (metadata order):
//   d_in[0] context_idxs  int32 [B, C]   B=65536, C=10
//   d_in[1] path_nodes    int32 [B, D]   D=18
//   d_in[2] codes         int32 [B, D]
//   d_in[3] in_embed      f32   [V, E]   V=100000, E=128
//   d_in[4] node_embed    f32   [N, E]   N=99999
// Output: loss f32 [B]
//
// R17 = R16 (fp16 tables, paired LDG.128, half2 math, wave-scheduled regs)
//       with two final squeezes:
//       (1) node gathers in 3 waves of 3 (peak resident data 32 regs vs 36)
//           + launch_bounds(256,6) -> target 42 regs = 48 warps/SM (75% occ);
//       (2) convert kernel: __ldcs streaming reads of the f32 tables +
//           default write-back stores of the fp16 tables, so the 51MB fp16
//           result is L2-resident when main launches (kills main's DRAM
//           fills; main DRAM was 19.9%).

#define B_ 65536
#define C_ 10
#define D_ 18
#define E_ 128
#define V_ 100000
#define N_ 99999
#define EPS_ 1e-9f

// fp16 tables (scratch). Row = E_/8 = 16 uint4 = 128 halves = 256B.
__device__ uint4 g_in16[V_ * E_ / 8];   // 25.6 MB
__device__ uint4 g_nd16[N_ * E_ / 8];   // 25.6 MB

__device__ __forceinline__ __half2 as_h2(unsigned u) {
    return *reinterpret_cast<__half2*>(&u);
}

// ---------------- prologue: f32 tables -> fp16 scratch ----------------
// Streaming reads (evict-first) of the f32 source; default write-back stores
// so the fp16 tables stay resident in L2 for the main kernel.
__global__ void __launch_bounds__(256) convert_kernel(
    const float4* __restrict__ inA,   // in_embed, V_*E_/4 float4
    const float4* __restrict__ inB)   // node_embed, N_*E_/4 float4
{
    const int nA8 = V_ * E_ / 8;              // uint4 count for in_embed
    const int nTot = nA8 + N_ * E_ / 8;
    int i = blockIdx.x * blockDim.x + threadIdx.x;
    if (i >= nTot) return;

    const float4* src;
    uint4* dst;
    if (i < nA8) {
        src = inA + 2 * (size_t)i;
        dst = &g_in16[i];
    } else {
        src = inB + 2 * (size_t)(i - nA8);
        dst = &g_nd16[i - nA8];
    }
    float4 f0 = __ldcs(src);          // streaming: don't pollute L2
    float4 f1 = __ldcs(src + 1);
    __half2 h0 = __floats2half2_rn(f0.x, f0.y);
    __half2 h1 = __floats2half2_rn(f0.z, f0.w);
    __half2 h2 = __floats2half2_rn(f1.x, f1.y);
    __half2 h3 = __floats2half2_rn(f1.z, f1.w);
    uint4 o;
    o.x = *reinterpret_cast<unsigned*>(&h0);
    o.y = *reinterpret_cast<unsigned*>(&h1);
    o.z = *reinterpret_cast<unsigned*>(&h2);
    o.w = *reinterpret_cast<unsigned*>(&h3);
    *dst = o;                          // write-back: keep fp16 in L2
}

// ---------------- main: paired LDG.128 fp16 gathers, half2 math ----------------
__global__ void __launch_bounds__(256, 6) cbow_hs_kernel(
    const int* __restrict__ ctx,
    const int* __restrict__ path,
    const int* __restrict__ codes,
    float* __restrict__ out)
{
    const int warp = (blockIdx.x * blockDim.x + threadIdx.x) >> 5;
    const int lane = threadIdx.x & 31;
    if (warp >= B_) return;

    const int half   = lane >> 4;        // 0: even row of pair, 1: odd row
    const int lane16 = lane & 15;        // 16B slice within the 256B row

    const uint4* __restrict__ in16 = g_in16;   // row = 16 uint4
    const uint4* __restrict__ nd16 = g_nd16;

    // ---- per-lane code: one coalesced 72B LDG per warp ----
    int code_l = 0;
    if (lane < D_) code_l = __ldg(&codes[warp * D_ + lane]);

    // ---- indices: per-lane row selection by half ----
    const int2* __restrict__ ctx2 = reinterpret_cast<const int2*>(ctx + warp * C_);
    const int2* __restrict__ pn2  = reinterpret_cast<const int2*>(path + warp * D_);
    int csel[C_ / 2];
#pragma unroll
    for (int j = 0; j < C_ / 2; j++) {
        int2 c = __ldg(&ctx2[j]);
        csel[j] = half ? c.y : c.x;
    }
    int psel[D_ / 2];
#pragma unroll
    for (int j = 0; j < D_ / 2; j++) {
        int2 p = __ldg(&pn2[j]);
        psel[j] = half ? p.y : p.x;
    }

    // ---- wave 1: ctx rows (5 paired LDG.128 = 20 regs) ----
    uint4 ce[C_ / 2];
#pragma unroll
    for (int j = 0; j < C_ / 2; j++)
        ce[j] = __ldg(&in16[(size_t)csel[j] * (E_ / 8) + lane16]);

    // ---- node wave 0: pairs 0..2 (12 regs) in flight ----
    uint4 nu0[3];
#pragma unroll
    for (int j = 0; j < 3; j++)
        nu0[j] = __ldg(&nd16[(size_t)psel[j] * (E_ / 8) + lane16]);

    // ---- consume ce into half2 mean accumulators (frees 20 regs) ----
    __half2 hv0 = as_h2(ce[0].x), hv1 = as_h2(ce[0].y);
    __half2 hv2 = as_h2(ce[0].z), hv3 = as_h2(ce[0].w);
#pragma unroll
    for (int j = 1; j < C_ / 2; j++) {
        hv0 = __hadd2(hv0, as_h2(ce[j].x));
        hv1 = __hadd2(hv1, as_h2(ce[j].y));
        hv2 = __hadd2(hv2, as_h2(ce[j].z));
        hv3 = __hadd2(hv3, as_h2(ce[j].w));
    }

    // ---- node wave 1: pairs 3..5 in flight ----
    uint4 nu1[3];
#pragma unroll
    for (int j = 0; j < 3; j++)
        nu1[j] = __ldg(&nd16[(size_t)psel[3 + j] * (E_ / 8) + lane16]);

    // ---- finish mean: cross-half reduce + scale in fp32 ----
    float v[8];
    {
        float2 a = __half22float2(hv0), b = __half22float2(hv1);
        float2 c = __half22float2(hv2), d = __half22float2(hv3);
        v[0] = a.x; v[1] = a.y; v[2] = b.x; v[3] = b.y;
        v[4] = c.x; v[5] = c.y; v[6] = d.x; v[7] = d.y;
    }
    const float inv = 1.0f / (float)C_;
#pragma unroll
    for (int k = 0; k < 8; k++) {
        v[k] += __shfl_xor_sync(0xFFFFFFFFu, v[k], 16);
        v[k] *= inv;
    }
    __half2 vh0 = __floats2half2_rn(v[0], v[1]);
    __half2 vh1 = __floats2half2_rn(v[2], v[3]);
    __half2 vh2 = __floats2half2_rn(v[4], v[5]);
    __half2 vh3 = __floats2half2_rn(v[6], v[7]);

    // ---- node wave 2: pairs 6..8 in flight ----
    uint4 nu2[3];
#pragma unroll
    for (int j = 0; j < 3; j++)
        nu2[j] = __ldg(&nd16[(size_t)psel[6 + j] * (E_ / 8) + lane16]);

    // ---- consume node waves (HFMA2 chains) ----
    float part[D_ / 2];
#pragma unroll
    for (int j = 0; j < 3; j++) {
        __half2 acc = __hmul2(as_h2(nu0[j].x), vh0);
        acc = __hfma2(as_h2(nu0[j].y), vh1, acc);
        acc = __hfma2(as_h2(nu0[j].z), vh2, acc);
        acc = __hfma2(as_h2(nu0[j].w), vh3, acc);
        float2 f = __half22float2(acc);
        part[j] = f.x + f.y;
    }
#pragma unroll
    for (int j = 0; j < 3; j++) {
        __half2 acc = __hmul2(as_h2(nu1[j].x), vh0);
        acc = __hfma2(as_h2(nu1[j].y), vh1, acc);
        acc = __hfma2(as_h2(nu1[j].z), vh2, acc);
        acc = __hfma2(as_h2(nu1[j].w), vh3, acc);
        float2 f = __half22float2(acc);
        part[3 + j] = f.x + f.y;
    }
#pragma unroll
    for (int j = 0; j < 3; j++) {
        __half2 acc = __hmul2(as_h2(nu2[j].x), vh0);
        acc = __hfma2(as_h2(nu2[j].y), vh1, acc);
        acc = __hfma2(as_h2(nu2[j].z), vh2, acc);
        acc = __hfma2(as_h2(nu2[j].w), vh3, acc);
        float2 f = __half22float2(acc);
        part[6 + j] = f.x + f.y;
    }

    // ---- 4-step butterfly within half-warp (fp32) ----
#pragma unroll
    for (int o = 8; o > 0; o >>= 1) {
#pragma unroll
        for (int j = 0; j < D_ / 2; j++)
            part[j] += __shfl_xor_sync(0xFFFFFFFFu, part[j], o);
    }

    // ---- route s_d to lane d (R6/R14 scheme) ----
    const int sel = lane & 15;
    float prep = part[0];
#pragma unroll
    for (int j = 1; j < D_ / 2; j++)
        prep = (sel == j) ? part[j] : prep;
    float s = __shfl_sync(0xFFFFFFFFu, prep, ((lane & 1) << 4) | (lane >> 1));

    // ---- epilogue once per warp (3 MUFU total) ----
    float x = code_l ? s : -s;   // p = sigmoid(x) if code==1 else sigmoid(-x)
    float sig = __fdividef(1.0f, 1.0f + __expf(-x));
    float term = __logf(sig + EPS_);
    term = (lane < D_) ? term : 0.f;

#pragma unroll
    for (int o = 16; o > 0; o >>= 1)
        term += __shfl_xor_sync(0xFFFFFFFFu, term, o);

    if (lane == 0)
        out[warp] = -term;
}

extern "C" void kernel_launch(void* const* d_in, const int* in_sizes, int n_in,
                              void* d_out, int out_size)
{
    const int*   ctx      = (const int*)d_in[0];
    const int*   path     = (const int*)d_in[1];
    const int*   codes    = (const int*)d_in[2];
    const float* in_emb   = (const float*)d_in[3];
    const float* node_emb = (const float*)d_in[4];
    float*       out      = (float*)d_out;

    // 1) convert both tables to fp16 scratch (L2-resident result)
    {
        const int nTot = (V_ + N_) * E_ / 8;   // uint4 count
        const int threads = 256;
        const int blocks = (nTot + threads - 1) / threads;
        convert_kernel<<<blocks, threads>>>(
            reinterpret_cast<const float4*>(in_emb),
            reinterpret_cast<const float4*>(node_emb));
    }

    // 2) main gather pass on fp16 rows (paired LDG.128, half2 math)
    {
        const int threads = 256;               // 8 warps/block
        const int total   = B_ * 32;
        const int blocks  = (total + threads - 1) / threads;
        cbow_hs_kernel<<<blocks, threads>>>(ctx, path, codes, out);
    }
}